// round 1
// baseline (speedup 1.0000x reference)
#include <cuda_runtime.h>
#include <math.h>

#define D_MODEL 512
#define D_FF    512
#define TWO_FF  1024
#define N_EXP   16
#define TOPK    3
#define MAX_T   2048

#define BM 64
#define BN 64
#define BK 16

// ---- static scratch (no dynamic allocation allowed) ----
__device__ int   g_cnt[N_EXP];
__device__ int   g_off[N_EXP + 1];
__device__ int   g_list[N_EXP * MAX_T];
__device__ float g_gate[N_EXP * MAX_T];
__device__ float g_Hs[MAX_T * D_FF];             // shared-expert hidden
__device__ float g_Hr[MAX_T * TOPK * D_FF];      // routed hidden (compact rows)

__global__ void reset_kernel() {
    if (threadIdx.x < N_EXP) g_cnt[threadIdx.x] = 0;
}

// One warp per token: 16 logits (D=512 dots), sigmoid, top-3, gating, scatter.
__global__ __launch_bounds__(256) void router_kernel(
    const float* __restrict__ x, const float* __restrict__ gw,
    const float* __restrict__ bias, int T)
{
    int w    = threadIdx.x >> 5;
    int lane = threadIdx.x & 31;
    int t    = blockIdx.x * 8 + w;
    if (t >= T) return;

    const float* xr = x + (size_t)t * D_MODEL;
    float xv[16];
#pragma unroll
    for (int i = 0; i < 16; i++) xv[i] = xr[lane + 32 * i];

    __shared__ float aff_s[8][N_EXP];
    for (int e = 0; e < N_EXP; e++) {
        const float* wr = gw + (size_t)e * D_MODEL;
        float p = 0.f;
#pragma unroll
        for (int i = 0; i < 16; i++) p += xv[i] * wr[lane + 32 * i];
#pragma unroll
        for (int o = 16; o; o >>= 1) p += __shfl_xor_sync(0xffffffffu, p, o);
        if (lane == 0) aff_s[w][e] = 1.f / (1.f + expf(-p));
    }
    __syncwarp();

    if (lane == 0) {
        float aff[N_EXP], sc[N_EXP];
        bool used[N_EXP];
#pragma unroll
        for (int e = 0; e < N_EXP; e++) {
            aff[e] = aff_s[w][e];
            sc[e]  = aff[e] + bias[e];
            used[e] = false;
        }
        int   sel[TOPK];
        float sa[TOPK];
        float ssum = 0.f;
        for (int k = 0; k < TOPK; k++) {
            int best = -1; float bv = -1e30f;
            for (int e = 0; e < N_EXP; e++)
                if (!used[e] && sc[e] > bv) { bv = sc[e]; best = e; }
            used[best] = true;
            sel[k] = best; sa[k] = aff[best]; ssum += aff[best];
        }
        float inv = 1.f / (ssum + 1e-9f);
        for (int k = 0; k < TOPK; k++) {
            int e   = sel[k];
            int pos = atomicAdd(&g_cnt[e], 1);
            g_list[e * MAX_T + pos] = t;
            g_gate[e * MAX_T + pos] = sa[k] * inv;
        }
    }
}

__global__ void scan_kernel() {
    int s = 0;
    for (int e = 0; e < N_EXP; e++) { g_off[e] = s; s += g_cnt[e]; }
    g_off[N_EXP] = s;
}

// Fused gate_up GEMM + SwiGLU (+ gating scale for routed).
// H[r, f] = gating * silu(x.Wg[f]) * (x.Wu[f])
template <bool ROUTED>
__global__ __launch_bounds__(256) void gu_kernel(
    const float* __restrict__ x,
    const float* __restrict__ Wsh,
    const float* __restrict__ Wexp, int T)
{
    __shared__ float As[BK][BM];
    __shared__ float Bg[BK][BN];
    __shared__ float Bu[BK][BN];
    __shared__ int   tok_s[BM];
    __shared__ float gsc_s[BM];

    int tid = threadIdx.x;
    int m0  = blockIdx.x * BM;
    int f0  = blockIdx.y * BN;

    const float* W;
    int cnt, roff = 0;
    if (ROUTED) {
        int e = blockIdx.z;
        int c = g_cnt[e];
        if (m0 >= c) return;
        cnt  = min(BM, c - m0);
        roff = g_off[e];
        W    = Wexp + (size_t)e * TWO_FF * D_MODEL;
        if (tid < BM) {
            if (tid < cnt) {
                tok_s[tid] = g_list[blockIdx.z * MAX_T + m0 + tid];
                gsc_s[tid] = g_gate[blockIdx.z * MAX_T + m0 + tid];
            } else { tok_s[tid] = 0; gsc_s[tid] = 0.f; }
        }
    } else {
        cnt = min(BM, T - m0);
        W   = Wsh;
        if (tid < BM) { tok_s[tid] = m0 + tid; gsc_s[tid] = 1.f; }
    }
    __syncthreads();

    int lr = tid >> 2;          // load row 0..63
    int lc = (tid & 3) * 4;     // 0,4,8,12

    int ty = tid >> 4;          // 0..15
    int tx = tid & 15;          // 0..15

    float ag[4][4] = {};
    float au[4][4] = {};

    bool rv = (lr < cnt);
    const float* xrow  = x + (size_t)tok_s[lr] * D_MODEL;
    const float* wgrow = W + (size_t)(f0 + lr) * D_MODEL;
    const float* wurow = W + (size_t)(f0 + lr + D_FF) * D_MODEL;

    for (int kk = 0; kk < D_MODEL; kk += BK) {
        float4 av  = rv ? *(const float4*)(xrow + kk + lc) : make_float4(0,0,0,0);
        float4 bgv = *(const float4*)(wgrow + kk + lc);
        float4 buv = *(const float4*)(wurow + kk + lc);
        As[lc + 0][lr] = av.x;  As[lc + 1][lr] = av.y;
        As[lc + 2][lr] = av.z;  As[lc + 3][lr] = av.w;
        Bg[lc + 0][lr] = bgv.x; Bg[lc + 1][lr] = bgv.y;
        Bg[lc + 2][lr] = bgv.z; Bg[lc + 3][lr] = bgv.w;
        Bu[lc + 0][lr] = buv.x; Bu[lc + 1][lr] = buv.y;
        Bu[lc + 2][lr] = buv.z; Bu[lc + 3][lr] = buv.w;
        __syncthreads();
#pragma unroll
        for (int k = 0; k < BK; k++) {
            float4 a  = *(const float4*)&As[k][ty * 4];
            float4 bg = *(const float4*)&Bg[k][tx * 4];
            float4 bu = *(const float4*)&Bu[k][tx * 4];
            float aa[4]  = {a.x, a.y, a.z, a.w};
            float bgA[4] = {bg.x, bg.y, bg.z, bg.w};
            float buA[4] = {bu.x, bu.y, bu.z, bu.w};
#pragma unroll
            for (int i = 0; i < 4; i++)
#pragma unroll
                for (int j = 0; j < 4; j++) {
                    ag[i][j] += aa[i] * bgA[j];
                    au[i][j] += aa[i] * buA[j];
                }
        }
        __syncthreads();
    }

    float* Hout = ROUTED ? (g_Hr + (size_t)(roff + m0) * D_FF)
                         : (g_Hs + (size_t)m0 * D_FF);
#pragma unroll
    for (int i = 0; i < 4; i++) {
        int r = ty * 4 + i;
        if (r >= cnt) continue;
        float gs = gsc_s[r];
        float4 hv;
        float* h = &hv.x;
#pragma unroll
        for (int j = 0; j < 4; j++) {
            float gv = ag[i][j];
            h[j] = gv / (1.f + expf(-gv)) * au[i][j] * gs;
        }
        *(float4*)(Hout + (size_t)r * D_FF + f0 + tx * 4) = hv;
    }
}

// Down projection: out[t, d] = sum_f H[r, f] * Wd[d, f]
// Shared path stores (initializes out); routed path atomicAdds.
template <bool ROUTED>
__global__ __launch_bounds__(256) void down_kernel(
    const float* __restrict__ Wsh,
    const float* __restrict__ Wexp,
    float* __restrict__ out, int T)
{
    __shared__ float As[BK][BM];
    __shared__ float Bs[BK][BN];
    __shared__ int   tok_s[BM];

    int tid = threadIdx.x;
    int m0  = blockIdx.x * BM;
    int d0  = blockIdx.y * BN;

    const float* W;
    const float* H;
    int cnt;
    if (ROUTED) {
        int e = blockIdx.z;
        int c = g_cnt[e];
        if (m0 >= c) return;
        cnt = min(BM, c - m0);
        W   = Wexp + (size_t)e * D_MODEL * D_FF;
        H   = g_Hr + (size_t)(g_off[e] + m0) * D_FF;
        if (tid < BM) tok_s[tid] = (tid < cnt) ? g_list[e * MAX_T + m0 + tid] : 0;
    } else {
        cnt = min(BM, T - m0);
        W   = Wsh;
        H   = g_Hs + (size_t)m0 * D_FF;
        if (tid < BM) tok_s[tid] = m0 + tid;
    }
    __syncthreads();

    int lr = tid >> 2;
    int lc = (tid & 3) * 4;
    int ty = tid >> 4;
    int tx = tid & 15;

    float acc[4][4] = {};
    bool rv = (lr < cnt);
    const float* hrow = H + (size_t)lr * D_FF;
    const float* wrow = W + (size_t)(d0 + lr) * D_FF;

    for (int kk = 0; kk < D_FF; kk += BK) {
        float4 av = rv ? *(const float4*)(hrow + kk + lc) : make_float4(0,0,0,0);
        float4 bv = *(const float4*)(wrow + kk + lc);
        As[lc + 0][lr] = av.x; As[lc + 1][lr] = av.y;
        As[lc + 2][lr] = av.z; As[lc + 3][lr] = av.w;
        Bs[lc + 0][lr] = bv.x; Bs[lc + 1][lr] = bv.y;
        Bs[lc + 2][lr] = bv.z; Bs[lc + 3][lr] = bv.w;
        __syncthreads();
#pragma unroll
        for (int k = 0; k < BK; k++) {
            float4 a = *(const float4*)&As[k][ty * 4];
            float4 b = *(const float4*)&Bs[k][tx * 4];
            float aa[4] = {a.x, a.y, a.z, a.w};
            float bb[4] = {b.x, b.y, b.z, b.w};
#pragma unroll
            for (int i = 0; i < 4; i++)
#pragma unroll
                for (int j = 0; j < 4; j++)
                    acc[i][j] += aa[i] * bb[j];
        }
        __syncthreads();
    }

#pragma unroll
    for (int i = 0; i < 4; i++) {
        int r = ty * 4 + i;
        if (r >= cnt) continue;
        int t = tok_s[r];
        float* orow = out + (size_t)t * D_MODEL + d0 + tx * 4;
        if (ROUTED) {
#pragma unroll
            for (int j = 0; j < 4; j++) atomicAdd(orow + j, acc[i][j]);
        } else {
            float4 v = make_float4(acc[i][0], acc[i][1], acc[i][2], acc[i][3]);
            *(float4*)orow = v;
        }
    }
}

extern "C" void kernel_launch(void* const* d_in, const int* in_sizes, int n_in,
                              void* d_out, int out_size)
{
    const float* x    = (const float*)d_in[0];
    const float* gw   = (const float*)d_in[1];
    const float* bias = (const float*)d_in[2];
    const float* sgu  = (const float*)d_in[3];
    const float* sdn  = (const float*)d_in[4];
    const float* egu  = (const float*)d_in[5];
    const float* edn  = (const float*)d_in[6];
    float* out = (float*)d_out;
    int T = in_sizes[0] / D_MODEL;

    reset_kernel<<<1, 32>>>();
    router_kernel<<<(T + 7) / 8, 256>>>(x, gw, bias, T);
    scan_kernel<<<1, 1>>>();

    dim3 blk(256);
    // shared expert
    gu_kernel<false><<<dim3(T / BM, D_FF / BN, 1), blk>>>(x, sgu, egu, T);
    down_kernel<false><<<dim3(T / BM, D_MODEL / BN, 1), blk>>>(sdn, edn, out, T);
    // routed experts (sparse: only selected tokens per expert)
    gu_kernel<true><<<dim3(T / BM, D_FF / BN, N_EXP), blk>>>(x, sgu, egu, T);
    down_kernel<true><<<dim3(T / BM, D_MODEL / BN, N_EXP), blk>>>(sdn, edn, out, T);
}

// round 4
// speedup vs baseline: 2.1960x; 2.1960x over previous
#include <cuda_runtime.h>
#include <cuda_bf16.h>
#include <math.h>
#include <stdint.h>

#define D_MODEL 512
#define D_FF    512
#define N_EXP   16
#define TOPK    3
#define MAX_T   2048
#define HROWS   (MAX_T + MAX_T * TOPK + 128)

#define TM   128
#define KC   64                 // bf16 elements per K chunk (128 bytes/row)
#define NCH  8                  // 512 / 64
#define TILE_B  (TM * 128)      // 16 KB per tile
#define STAGE_B (4 * TILE_B)    // Ah, Al, Bh, Bl
#define DYN_B   (2 * STAGE_B + 1024)

#define SWZ(o) ((o) ^ (((o) >> 3) & 0x70))

// ---------------- static scratch ----------------
__device__ int   g_cnt[N_EXP];
__device__ int   g_off[N_EXP + 1];
__device__ int   g_list[N_EXP * MAX_T];
__device__ float g_gate[N_EXP * MAX_T];

__device__ __align__(256) __nv_bfloat16 g_xh[MAX_T * D_MODEL];
__device__ __align__(256) __nv_bfloat16 g_xl[MAX_T * D_MODEL];
__device__ __align__(256) __nv_bfloat16 g_sguh[2 * D_FF * D_MODEL];
__device__ __align__(256) __nv_bfloat16 g_sgul[2 * D_FF * D_MODEL];
__device__ __align__(256) __nv_bfloat16 g_sdnh[D_MODEL * D_FF];
__device__ __align__(256) __nv_bfloat16 g_sdnl[D_MODEL * D_FF];
__device__ __align__(256) __nv_bfloat16 g_eguh[N_EXP * 2 * D_FF * D_MODEL];
__device__ __align__(256) __nv_bfloat16 g_egul[N_EXP * 2 * D_FF * D_MODEL];
__device__ __align__(256) __nv_bfloat16 g_ednh[N_EXP * D_MODEL * D_FF];
__device__ __align__(256) __nv_bfloat16 g_ednl[N_EXP * D_MODEL * D_FF];
__device__ __align__(256) __nv_bfloat16 g_Hh[(size_t)HROWS * D_FF];
__device__ __align__(256) __nv_bfloat16 g_Hl[(size_t)HROWS * D_FF];

// ---------------- PTX helpers ----------------
__device__ __forceinline__ uint32_t smem_u32(const void* p) {
    uint32_t a;
    asm("{ .reg .u64 t; cvta.to.shared.u64 t, %1; cvt.u32.u64 %0, t; }" : "=r"(a) : "l"(p));
    return a;
}
__device__ __forceinline__ void cp16(uint32_t s, const void* g) {
    asm volatile("cp.async.cg.shared.global [%0], [%1], 16;" :: "r"(s), "l"(g));
}
#define CP_COMMIT() asm volatile("cp.async.commit_group;")
#define CP_WAIT(n)  asm volatile("cp.async.wait_group %0;" :: "n"(n))

__device__ __forceinline__ void ldm4(uint32_t* r, uint32_t a) {
    asm volatile("ldmatrix.sync.aligned.m8n8.x4.shared.b16 {%0,%1,%2,%3}, [%4];"
                 : "=r"(r[0]), "=r"(r[1]), "=r"(r[2]), "=r"(r[3]) : "r"(a));
}
__device__ __forceinline__ void mma16816(float* c, const uint32_t* a, uint32_t b0, uint32_t b1) {
    asm volatile("mma.sync.aligned.m16n8k16.row.col.f32.bf16.bf16.f32 "
                 "{%0,%1,%2,%3}, {%4,%5,%6,%7}, {%8,%9}, {%0,%1,%2,%3};"
                 : "+f"(c[0]), "+f"(c[1]), "+f"(c[2]), "+f"(c[3])
                 : "r"(a[0]), "r"(a[1]), "r"(a[2]), "r"(a[3]), "r"(b0), "r"(b1));
}

// ---------------- small kernels ----------------
__global__ void reset_kernel() {
    if (threadIdx.x < N_EXP) g_cnt[threadIdx.x] = 0;
}

__device__ __forceinline__ uint32_t pack2(float a, float b) {
    __nv_bfloat16 x = __float2bfloat16(a), y = __float2bfloat16(b);
    return ((uint32_t)__bfloat16_as_ushort(y) << 16) | __bfloat16_as_ushort(x);
}

__global__ __launch_bounds__(256) void split4_kernel(
    const float* __restrict__ src, __nv_bfloat16* __restrict__ h,
    __nv_bfloat16* __restrict__ l, int n)
{
    int i = (blockIdx.x * 256 + threadIdx.x) * 4;
    if (i < n) {
        float4 v = *(const float4*)(src + i);
        __nv_bfloat16 h0 = __float2bfloat16(v.x), h1 = __float2bfloat16(v.y);
        __nv_bfloat16 h2 = __float2bfloat16(v.z), h3 = __float2bfloat16(v.w);
        uint2 hv, lv;
        hv.x = ((uint32_t)__bfloat16_as_ushort(h1) << 16) | __bfloat16_as_ushort(h0);
        hv.y = ((uint32_t)__bfloat16_as_ushort(h3) << 16) | __bfloat16_as_ushort(h2);
        lv.x = pack2(v.x - __bfloat162float(h0), v.y - __bfloat162float(h1));
        lv.y = pack2(v.z - __bfloat162float(h2), v.w - __bfloat162float(h3));
        *(uint2*)(h + i) = hv;
        *(uint2*)(l + i) = lv;
    }
}

__global__ __launch_bounds__(256) void router_kernel(
    const float* __restrict__ x, const float* __restrict__ gw,
    const float* __restrict__ bias, int T)
{
    int w    = threadIdx.x >> 5;
    int lane = threadIdx.x & 31;
    int t    = blockIdx.x * 8 + w;
    if (t >= T) return;

    const float* xr = x + (size_t)t * D_MODEL;
    float xv[16];
#pragma unroll
    for (int i = 0; i < 16; i++) xv[i] = xr[lane + 32 * i];

    __shared__ float aff_s[8][N_EXP];
    for (int e = 0; e < N_EXP; e++) {
        const float* wr = gw + (size_t)e * D_MODEL;
        float p = 0.f;
#pragma unroll
        for (int i = 0; i < 16; i++) p += xv[i] * wr[lane + 32 * i];
#pragma unroll
        for (int o = 16; o; o >>= 1) p += __shfl_xor_sync(0xffffffffu, p, o);
        if (lane == 0) aff_s[w][e] = 1.f / (1.f + expf(-p));
    }
    __syncwarp();

    if (lane == 0) {
        float aff[N_EXP], sc[N_EXP];
        bool used[N_EXP];
#pragma unroll
        for (int e = 0; e < N_EXP; e++) {
            aff[e] = aff_s[w][e];
            sc[e]  = aff[e] + bias[e];
            used[e] = false;
        }
        int   sel[TOPK];
        float sa[TOPK];
        float ssum = 0.f;
        for (int k = 0; k < TOPK; k++) {
            int best = -1; float bv = -1e30f;
            for (int e = 0; e < N_EXP; e++)
                if (!used[e] && sc[e] > bv) { bv = sc[e]; best = e; }
            used[best] = true;
            sel[k] = best; sa[k] = aff[best]; ssum += aff[best];
        }
        float inv = 1.f / (ssum + 1e-9f);
        for (int k = 0; k < TOPK; k++) {
            int e   = sel[k];
            int pos = atomicAdd(&g_cnt[e], 1);
            g_list[e * MAX_T + pos] = t;
            g_gate[e * MAX_T + pos] = sa[k] * inv;
        }
    }
}

__global__ void scan_kernel() {
    int s = 0;
    for (int e = 0; e < N_EXP; e++) { g_off[e] = s; s += g_cnt[e]; }
    g_off[N_EXP] = s;
}

// ---------------- GEMM 1: x @ Wgu^T -> SwiGLU -> H (bf16 hi/lo) ----------------
// B tile is interleaved: row 2j = gate feature f0+j, row 2j+1 = up feature f0+j
__global__ __launch_bounds__(256, 1) void gu_mma(int T)
{
    __shared__ int   tok_s[TM];
    __shared__ float gsc_s[TM];
    extern __shared__ __align__(16) char dynraw[];

    int z  = blockIdx.z;
    int m0 = blockIdx.x * TM;
    int f0 = blockIdx.y * 64;       // 64 features per block (128 interleaved B rows)
    int tid = threadIdx.x, wid = tid >> 5, lane = tid & 31;
    int warpM = wid >> 2, warpN = wid & 3;

    int cnt, hbase;
    const __nv_bfloat16 *Wh, *Wl;
    if (z < N_EXP) {
        int c = g_cnt[z];
        if (m0 >= c) return;
        cnt   = min(TM, c - m0);
        Wh    = g_eguh + (size_t)z * 2 * D_FF * D_MODEL;
        Wl    = g_egul + (size_t)z * 2 * D_FF * D_MODEL;
        hbase = MAX_T + g_off[z] + m0;
        if (tid < TM) {
            if (tid < cnt) {
                tok_s[tid] = g_list[z * MAX_T + m0 + tid];
                gsc_s[tid] = g_gate[z * MAX_T + m0 + tid];
            } else { tok_s[tid] = 0; gsc_s[tid] = 0.f; }
        }
    } else {
        if (m0 >= T) return;
        cnt   = min(TM, T - m0);
        Wh    = g_sguh; Wl = g_sgul;
        hbase = m0;
        if (tid < TM) { tok_s[tid] = m0 + tid; gsc_s[tid] = 1.f; }
    }
    __syncthreads();

    char*    dynp = (char*)(((uintptr_t)dynraw + 1023) & ~(uintptr_t)1023);
    uint32_t sb   = smem_u32(dynp);

    auto load_stage = [&](int s) {
        int kk = s * KC;
        uint32_t base = sb + (s & 1) * STAGE_B;
#pragma unroll
        for (int j = 0; j < 4; j++) {
            int within = tid + j * 256;
            int row = within >> 3, col = within & 7;
            uint32_t so = SWZ(row * 128 + col * 16);
            size_t xo = (size_t)tok_s[row] * D_MODEL + kk + col * 8;
            cp16(base + so,          g_xh + xo);
            cp16(base + TILE_B + so, g_xl + xo);
            int wr = (row & 1) ? (D_FF + f0 + (row >> 1)) : (f0 + (row >> 1));
            size_t wo = (size_t)wr * D_MODEL + kk + col * 8;
            cp16(base + 2 * TILE_B + so, Wh + wo);
            cp16(base + 3 * TILE_B + so, Wl + wo);
        }
        CP_COMMIT();
    };

    float acc[4][4][4] = {};

    load_stage(0);
    for (int s = 0; s < NCH; s++) {
        if (s + 1 < NCH) { load_stage(s + 1); CP_WAIT(1); }
        else             { CP_WAIT(0); }
        __syncthreads();
        uint32_t base = sb + (s & 1) * STAGE_B;
#pragma unroll
        for (int ks = 0; ks < 4; ks++) {
            int kb = ks * 32 + (lane >> 4) * 16;
            uint32_t aH[4][4], aL[4][4], bHr[2][4], bLr[2][4];
            int arow = warpM * 64 + (lane & 15);
#pragma unroll
            for (int mf = 0; mf < 4; mf++) {
                uint32_t off = SWZ((arow + mf * 16) * 128 + kb);
                ldm4(aH[mf], base + off);
                ldm4(aL[mf], base + TILE_B + off);
            }
            int brow = warpN * 32 + (lane & 15);
#pragma unroll
            for (int h = 0; h < 2; h++) {
                uint32_t off = SWZ((brow + h * 16) * 128 + kb);
                ldm4(bHr[h], base + 2 * TILE_B + off);
                ldm4(bLr[h], base + 3 * TILE_B + off);
            }
#pragma unroll
            for (int mf = 0; mf < 4; mf++)
#pragma unroll
                for (int h = 0; h < 2; h++)
#pragma unroll
                    for (int hf = 0; hf < 2; hf++) {
                        int nf = h * 2 + hf;
                        mma16816(acc[mf][nf], aH[mf], bHr[h][hf], bHr[h][hf + 2]);
                        mma16816(acc[mf][nf], aH[mf], bLr[h][hf], bLr[h][hf + 2]);
                        mma16816(acc[mf][nf], aL[mf], bHr[h][hf], bHr[h][hf + 2]);
                    }
        }
        __syncthreads();
    }

    // epilogue: (c even, c odd) = (gate, up) of one feature
#pragma unroll
    for (int mf = 0; mf < 4; mf++) {
        int rbase = warpM * 64 + mf * 16 + (lane >> 2);
#pragma unroll
        for (int rr = 0; rr < 2; rr++) {
            int r = rbase + rr * 8;
            if (r < cnt) {
                float gsc = gsc_s[r];
                size_t hrow = (size_t)(hbase + r) * D_FF;
#pragma unroll
                for (int h = 0; h < 2; h++)
#pragma unroll
                    for (int hf = 0; hf < 2; hf++) {
                        int nf = h * 2 + hf;
                        float g = acc[mf][nf][rr * 2 + 0];
                        float u = acc[mf][nf][rr * 2 + 1];
                        float hv = g / (1.f + __expf(-g)) * u * gsc;
                        __nv_bfloat16 hh = __float2bfloat16(hv);
                        __nv_bfloat16 hl = __float2bfloat16(hv - __bfloat162float(hh));
                        int f = f0 + warpN * 16 + h * 8 + hf * 4 + (lane & 3);
                        g_Hh[hrow + f] = hh;
                        g_Hl[hrow + f] = hl;
                    }
            }
        }
    }
}

// ---------------- GEMM 2: H @ Wd^T -> atomicAdd out ----------------
__global__ __launch_bounds__(256, 1) void down_mma(float* __restrict__ out, int T)
{
    __shared__ int tok_s[TM];
    extern __shared__ __align__(16) char dynraw[];

    int z  = blockIdx.z;
    int m0 = blockIdx.x * TM;
    int d0 = blockIdx.y * 128;
    int tid = threadIdx.x, wid = tid >> 5, lane = tid & 31;
    int warpM = wid >> 2, warpN = wid & 3;

    int cnt, hbase;
    const __nv_bfloat16 *Wh, *Wl;
    if (z < N_EXP) {
        int c = g_cnt[z];
        if (m0 >= c) return;
        cnt   = min(TM, c - m0);
        Wh    = g_ednh + (size_t)z * D_MODEL * D_FF;
        Wl    = g_ednl + (size_t)z * D_MODEL * D_FF;
        hbase = MAX_T + g_off[z] + m0;
        if (tid < TM) tok_s[tid] = (tid < cnt) ? g_list[z * MAX_T + m0 + tid] : 0;
    } else {
        if (m0 >= T) return;
        cnt   = min(TM, T - m0);
        Wh    = g_sdnh; Wl = g_sdnl;
        hbase = m0;
        if (tid < TM) tok_s[tid] = m0 + tid;
    }
    __syncthreads();

    char*    dynp = (char*)(((uintptr_t)dynraw + 1023) & ~(uintptr_t)1023);
    uint32_t sb   = smem_u32(dynp);

    auto load_stage = [&](int s) {
        int kk = s * KC;
        uint32_t base = sb + (s & 1) * STAGE_B;
#pragma unroll
        for (int j = 0; j < 4; j++) {
            int within = tid + j * 256;
            int row = within >> 3, col = within & 7;
            uint32_t so = SWZ(row * 128 + col * 16);
            size_t ho = (size_t)(hbase + row) * D_FF + kk + col * 8;
            cp16(base + so,          g_Hh + ho);
            cp16(base + TILE_B + so, g_Hl + ho);
            size_t wo = (size_t)(d0 + row) * D_FF + kk + col * 8;
            cp16(base + 2 * TILE_B + so, Wh + wo);
            cp16(base + 3 * TILE_B + so, Wl + wo);
        }
        CP_COMMIT();
    };

    float acc[4][4][4] = {};

    load_stage(0);
    for (int s = 0; s < NCH; s++) {
        if (s + 1 < NCH) { load_stage(s + 1); CP_WAIT(1); }
        else             { CP_WAIT(0); }
        __syncthreads();
        uint32_t base = sb + (s & 1) * STAGE_B;
#pragma unroll
        for (int ks = 0; ks < 4; ks++) {
            int kb = ks * 32 + (lane >> 4) * 16;
            uint32_t aH[4][4], aL[4][4], bHr[2][4], bLr[2][4];
            int arow = warpM * 64 + (lane & 15);
#pragma unroll
            for (int mf = 0; mf < 4; mf++) {
                uint32_t off = SWZ((arow + mf * 16) * 128 + kb);
                ldm4(aH[mf], base + off);
                ldm4(aL[mf], base + TILE_B + off);
            }
            int brow = warpN * 32 + (lane & 15);
#pragma unroll
            for (int h = 0; h < 2; h++) {
                uint32_t off = SWZ((brow + h * 16) * 128 + kb);
                ldm4(bHr[h], base + 2 * TILE_B + off);
                ldm4(bLr[h], base + 3 * TILE_B + off);
            }
#pragma unroll
            for (int mf = 0; mf < 4; mf++)
#pragma unroll
                for (int h = 0; h < 2; h++)
#pragma unroll
                    for (int hf = 0; hf < 2; hf++) {
                        int nf = h * 2 + hf;
                        mma16816(acc[mf][nf], aH[mf], bHr[h][hf], bHr[h][hf + 2]);
                        mma16816(acc[mf][nf], aH[mf], bLr[h][hf], bLr[h][hf + 2]);
                        mma16816(acc[mf][nf], aL[mf], bHr[h][hf], bHr[h][hf + 2]);
                    }
        }
        __syncthreads();
    }

#pragma unroll
    for (int mf = 0; mf < 4; mf++) {
        int rbase = warpM * 64 + mf * 16 + (lane >> 2);
#pragma unroll
        for (int rr = 0; rr < 2; rr++) {
            int r = rbase + rr * 8;
            if (r < cnt) {
                float* orow = out + (size_t)tok_s[r] * D_MODEL;
#pragma unroll
                for (int h = 0; h < 2; h++)
#pragma unroll
                    for (int hf = 0; hf < 2; hf++) {
                        int nf = h * 2 + hf;
                        int c  = d0 + warpN * 32 + h * 16 + hf * 8 + (lane & 3) * 2;
                        atomicAdd(orow + c,     acc[mf][nf][rr * 2 + 0]);
                        atomicAdd(orow + c + 1, acc[mf][nf][rr * 2 + 1]);
                    }
            }
        }
    }
}

// ---------------- launch ----------------
extern "C" void kernel_launch(void* const* d_in, const int* in_sizes, int n_in,
                              void* d_out, int out_size)
{
    const float* x    = (const float*)d_in[0];
    const float* gw   = (const float*)d_in[1];
    const float* bias = (const float*)d_in[2];
    const float* sgu  = (const float*)d_in[3];
    const float* sdn  = (const float*)d_in[4];
    const float* egu  = (const float*)d_in[5];
    const float* edn  = (const float*)d_in[6];
    float* out = (float*)d_out;
    int T = in_sizes[0] / D_MODEL;

    cudaFuncSetAttribute(gu_mma,   cudaFuncAttributeMaxDynamicSharedMemorySize, DYN_B);
    cudaFuncSetAttribute(down_mma, cudaFuncAttributeMaxDynamicSharedMemorySize, DYN_B);

    void *xh, *xl, *sguh, *sgul, *sdnh, *sdnl, *eguh, *egul, *ednh, *ednl;
    cudaGetSymbolAddress(&xh,   g_xh);   cudaGetSymbolAddress(&xl,   g_xl);
    cudaGetSymbolAddress(&sguh, g_sguh); cudaGetSymbolAddress(&sgul, g_sgul);
    cudaGetSymbolAddress(&sdnh, g_sdnh); cudaGetSymbolAddress(&sdnl, g_sdnl);
    cudaGetSymbolAddress(&eguh, g_eguh); cudaGetSymbolAddress(&egul, g_egul);
    cudaGetSymbolAddress(&ednh, g_ednh); cudaGetSymbolAddress(&ednl, g_ednl);

    reset_kernel<<<1, 32>>>();
    router_kernel<<<(T + 7) / 8, 256>>>(x, gw, bias, T);
    scan_kernel<<<1, 1>>>();

    int nx = T * D_MODEL;
    split4_kernel<<<(nx / 4 + 255) / 256, 256>>>(x, (__nv_bfloat16*)xh, (__nv_bfloat16*)xl, nx);
    int ngu = 2 * D_FF * D_MODEL;
    split4_kernel<<<(ngu / 4 + 255) / 256, 256>>>(sgu, (__nv_bfloat16*)sguh, (__nv_bfloat16*)sgul, ngu);
    int ndn = D_MODEL * D_FF;
    split4_kernel<<<(ndn / 4 + 255) / 256, 256>>>(sdn, (__nv_bfloat16*)sdnh, (__nv_bfloat16*)sdnl, ndn);
    int negu = N_EXP * 2 * D_FF * D_MODEL;
    split4_kernel<<<(negu / 4 + 255) / 256, 256>>>(egu, (__nv_bfloat16*)eguh, (__nv_bfloat16*)egul, negu);
    int nedn = N_EXP * D_MODEL * D_FF;
    split4_kernel<<<(nedn / 4 + 255) / 256, 256>>>(edn, (__nv_bfloat16*)ednh, (__nv_bfloat16*)ednl, nedn);

    cudaMemsetAsync(out, 0, (size_t)out_size * sizeof(float), 0);

    gu_mma<<<dim3(MAX_T / TM, D_FF / 64, N_EXP + 1), 256, DYN_B>>>(T);
    down_mma<<<dim3(MAX_T / TM, D_MODEL / 128, N_EXP + 1), 256, DYN_B>>>(out, T);
}

// round 5
// speedup vs baseline: 2.6859x; 1.2231x over previous
#include <cuda_runtime.h>
#include <cuda_fp16.h>
#include <math.h>
#include <stdint.h>

#define D_MODEL 512
#define D_FF    512
#define N_EXP   16
#define TOPK    3
#define MAX_T   2048
#define HROWS   (MAX_T + MAX_T * TOPK + 128)

#define TM   128
#define KC   64                 // fp16 elements per K chunk (128 bytes/row)
#define NCH  8                  // 512 / 64
#define TILE_B  (TM * 128)      // 16 KB per tile
#define STAGE_B (3 * TILE_B)    // Ah, Al, B
#define DYN_B   (2 * STAGE_B + 1024)

#define SWZ(o) ((o) ^ (((o) >> 3) & 0x70))

// ---------------- static scratch ----------------
__device__ int   g_cnt[N_EXP];
__device__ int   g_off[N_EXP + 1];
__device__ int   g_list[N_EXP * MAX_T];
__device__ float g_gate[N_EXP * MAX_T];

__device__ __align__(256) __half g_xh[MAX_T * D_MODEL];
__device__ __align__(256) __half g_xl[MAX_T * D_MODEL];
__device__ __align__(256) __half g_sguw[2 * D_FF * D_MODEL];
__device__ __align__(256) __half g_sdnw[D_MODEL * D_FF];
__device__ __align__(256) __half g_eguw[N_EXP * 2 * D_FF * D_MODEL];
__device__ __align__(256) __half g_ednw[N_EXP * D_MODEL * D_FF];
__device__ __align__(256) __half g_Hh[(size_t)HROWS * D_FF];
__device__ __align__(256) __half g_Hl[(size_t)HROWS * D_FF];

// ---------------- PTX helpers ----------------
__device__ __forceinline__ uint32_t smem_u32(const void* p) {
    uint32_t a;
    asm("{ .reg .u64 t; cvta.to.shared.u64 t, %1; cvt.u32.u64 %0, t; }" : "=r"(a) : "l"(p));
    return a;
}
__device__ __forceinline__ void cp16(uint32_t s, const void* g) {
    asm volatile("cp.async.cg.shared.global [%0], [%1], 16;" :: "r"(s), "l"(g));
}
#define CP_COMMIT() asm volatile("cp.async.commit_group;")
#define CP_WAIT(n)  asm volatile("cp.async.wait_group %0;" :: "n"(n))

__device__ __forceinline__ void ldm4(uint32_t* r, uint32_t a) {
    asm volatile("ldmatrix.sync.aligned.m8n8.x4.shared.b16 {%0,%1,%2,%3}, [%4];"
                 : "=r"(r[0]), "=r"(r[1]), "=r"(r[2]), "=r"(r[3]) : "r"(a));
}
__device__ __forceinline__ void mma16816(float* c, const uint32_t* a, uint32_t b0, uint32_t b1) {
    asm volatile("mma.sync.aligned.m16n8k16.row.col.f32.f16.f16.f32 "
                 "{%0,%1,%2,%3}, {%4,%5,%6,%7}, {%8,%9}, {%0,%1,%2,%3};"
                 : "+f"(c[0]), "+f"(c[1]), "+f"(c[2]), "+f"(c[3])
                 : "r"(a[0]), "r"(a[1]), "r"(a[2]), "r"(a[3]), "r"(b0), "r"(b1));
}

// ---------------- small kernels ----------------
__global__ void reset_kernel() {
    if (threadIdx.x < N_EXP) g_cnt[threadIdx.x] = 0;
}

// fp32 -> fp16 cast, 16 elements/thread, grid-stride (n multiple of 16)
__global__ __launch_bounds__(256) void conv16_kernel(
    const float* __restrict__ src, __half* __restrict__ dst, int n)
{
    int stride = gridDim.x * 256 * 16;
    for (int i0 = (blockIdx.x * 256 + threadIdx.x) * 16; i0 < n; i0 += stride) {
        float4 v[4];
#pragma unroll
        for (int q = 0; q < 4; q++) v[q] = *(const float4*)(src + i0 + q * 4);
        uint2 o[4];
#pragma unroll
        for (int q = 0; q < 4; q++) {
            __half2 p0 = __floats2half2_rn(v[q].x, v[q].y);
            __half2 p1 = __floats2half2_rn(v[q].z, v[q].w);
            o[q].x = *(uint32_t*)&p0;
            o[q].y = *(uint32_t*)&p1;
        }
        uint4 w0 = make_uint4(o[0].x, o[0].y, o[1].x, o[1].y);
        uint4 w1 = make_uint4(o[2].x, o[2].y, o[3].x, o[3].y);
        *(uint4*)(dst + i0)     = w0;
        *(uint4*)(dst + i0 + 8) = w1;
    }
}

// fp32 -> fp16 hi/lo split, 8 elements/thread, grid-stride
__global__ __launch_bounds__(256) void split8_kernel(
    const float* __restrict__ src, __half* __restrict__ h,
    __half* __restrict__ l, int n)
{
    int stride = gridDim.x * 256 * 8;
    for (int i0 = (blockIdx.x * 256 + threadIdx.x) * 8; i0 < n; i0 += stride) {
        float4 a = *(const float4*)(src + i0);
        float4 b = *(const float4*)(src + i0 + 4);
        float vv[8] = {a.x, a.y, a.z, a.w, b.x, b.y, b.z, b.w};
        __half hh[8], hl[8];
#pragma unroll
        for (int q = 0; q < 8; q++) {
            hh[q] = __float2half_rn(vv[q]);
            hl[q] = __float2half_rn(vv[q] - __half2float(hh[q]));
        }
        *(uint4*)(h + i0) = *(uint4*)hh;
        *(uint4*)(l + i0) = *(uint4*)hl;
    }
}

__global__ __launch_bounds__(256) void router_kernel(
    const float* __restrict__ x, const float* __restrict__ gw,
    const float* __restrict__ bias, int T)
{
    int w    = threadIdx.x >> 5;
    int lane = threadIdx.x & 31;
    int t    = blockIdx.x * 8 + w;
    if (t >= T) return;

    const float* xr = x + (size_t)t * D_MODEL;
    float xv[16];
#pragma unroll
    for (int i = 0; i < 16; i++) xv[i] = xr[lane + 32 * i];

    __shared__ float aff_s[8][N_EXP];
    for (int e = 0; e < N_EXP; e++) {
        const float* wr = gw + (size_t)e * D_MODEL;
        float p = 0.f;
#pragma unroll
        for (int i = 0; i < 16; i++) p += xv[i] * wr[lane + 32 * i];
#pragma unroll
        for (int o = 16; o; o >>= 1) p += __shfl_xor_sync(0xffffffffu, p, o);
        if (lane == 0) aff_s[w][e] = 1.f / (1.f + expf(-p));
    }
    __syncwarp();

    if (lane == 0) {
        float aff[N_EXP], sc[N_EXP];
        bool used[N_EXP];
#pragma unroll
        for (int e = 0; e < N_EXP; e++) {
            aff[e] = aff_s[w][e];
            sc[e]  = aff[e] + bias[e];
            used[e] = false;
        }
        int   sel[TOPK];
        float sa[TOPK];
        float ssum = 0.f;
        for (int k = 0; k < TOPK; k++) {
            int best = -1; float bv = -1e30f;
            for (int e = 0; e < N_EXP; e++)
                if (!used[e] && sc[e] > bv) { bv = sc[e]; best = e; }
            used[best] = true;
            sel[k] = best; sa[k] = aff[best]; ssum += aff[best];
        }
        float inv = 1.f / (ssum + 1e-9f);
        for (int k = 0; k < TOPK; k++) {
            int e   = sel[k];
            int pos = atomicAdd(&g_cnt[e], 1);
            g_list[e * MAX_T + pos] = t;
            g_gate[e * MAX_T + pos] = sa[k] * inv;
        }
    }
}

__global__ void scan_kernel() {
    int s = 0;
    for (int e = 0; e < N_EXP; e++) { g_off[e] = s; s += g_cnt[e]; }
    g_off[N_EXP] = s;
}

// ---------------- GEMM 1: x @ Wgu^T -> SwiGLU -> H (fp16 hi/lo) ----------------
// B tile is interleaved: row 2j = gate feature f0+j, row 2j+1 = up feature f0+j
__global__ __launch_bounds__(256, 1) void gu_mma(int T)
{
    __shared__ int   tok_s[TM];
    __shared__ float gsc_s[TM];
    extern __shared__ __align__(16) char dynraw[];

    int z  = blockIdx.z;
    int m0 = blockIdx.x * TM;
    int f0 = blockIdx.y * 64;       // 64 features per block (128 interleaved B rows)
    int tid = threadIdx.x, wid = tid >> 5, lane = tid & 31;
    int warpM = wid >> 2, warpN = wid & 3;

    int cnt, hbase;
    const __half* W;
    if (z < N_EXP) {
        int c = g_cnt[z];
        if (m0 >= c) return;
        cnt   = min(TM, c - m0);
        W     = g_eguw + (size_t)z * 2 * D_FF * D_MODEL;
        hbase = MAX_T + g_off[z] + m0;
        if (tid < TM) {
            if (tid < cnt) {
                tok_s[tid] = g_list[z * MAX_T + m0 + tid];
                gsc_s[tid] = g_gate[z * MAX_T + m0 + tid];
            } else { tok_s[tid] = 0; gsc_s[tid] = 0.f; }
        }
    } else {
        if (m0 >= T) return;
        cnt   = min(TM, T - m0);
        W     = g_sguw;
        hbase = m0;
        if (tid < TM) { tok_s[tid] = m0 + tid; gsc_s[tid] = 1.f; }
    }
    __syncthreads();

    char*    dynp = (char*)(((uintptr_t)dynraw + 1023) & ~(uintptr_t)1023);
    uint32_t sb   = smem_u32(dynp);

    auto load_stage = [&](int s) {
        int kk = s * KC;
        uint32_t base = sb + (s & 1) * STAGE_B;
#pragma unroll
        for (int j = 0; j < 4; j++) {
            int within = tid + j * 256;
            int row = within >> 3, col = within & 7;
            uint32_t so = SWZ(row * 128 + col * 16);
            size_t xo = (size_t)tok_s[row] * D_MODEL + kk + col * 8;
            cp16(base + so,          g_xh + xo);
            cp16(base + TILE_B + so, g_xl + xo);
            int wr = (row & 1) ? (D_FF + f0 + (row >> 1)) : (f0 + (row >> 1));
            size_t wo = (size_t)wr * D_MODEL + kk + col * 8;
            cp16(base + 2 * TILE_B + so, W + wo);
        }
        CP_COMMIT();
    };

    float acc[4][4][4] = {};

    load_stage(0);
    for (int s = 0; s < NCH; s++) {
        if (s + 1 < NCH) { load_stage(s + 1); CP_WAIT(1); }
        else             { CP_WAIT(0); }
        __syncthreads();
        uint32_t base = sb + (s & 1) * STAGE_B;
#pragma unroll
        for (int ks = 0; ks < 4; ks++) {
            int kb = ks * 32 + (lane >> 4) * 16;
            uint32_t aH[4][4], aL[4][4], br[2][4];
            int arow = warpM * 64 + (lane & 15);
#pragma unroll
            for (int mf = 0; mf < 4; mf++) {
                uint32_t off = SWZ((arow + mf * 16) * 128 + kb);
                ldm4(aH[mf], base + off);
                ldm4(aL[mf], base + TILE_B + off);
            }
            int brow = warpN * 32 + (lane & 15);
#pragma unroll
            for (int h = 0; h < 2; h++) {
                uint32_t off = SWZ((brow + h * 16) * 128 + kb);
                ldm4(br[h], base + 2 * TILE_B + off);
            }
#pragma unroll
            for (int mf = 0; mf < 4; mf++)
#pragma unroll
                for (int h = 0; h < 2; h++)
#pragma unroll
                    for (int hf = 0; hf < 2; hf++) {
                        int nf = h * 2 + hf;
                        mma16816(acc[mf][nf], aH[mf], br[h][hf], br[h][hf + 2]);
                        mma16816(acc[mf][nf], aL[mf], br[h][hf], br[h][hf + 2]);
                    }
        }
        __syncthreads();
    }

    // epilogue: (c even, c odd) = (gate, up) of one feature
#pragma unroll
    for (int mf = 0; mf < 4; mf++) {
        int rbase = warpM * 64 + mf * 16 + (lane >> 2);
#pragma unroll
        for (int rr = 0; rr < 2; rr++) {
            int r = rbase + rr * 8;
            if (r < cnt) {
                float gsc = gsc_s[r];
                size_t hrow = (size_t)(hbase + r) * D_FF;
#pragma unroll
                for (int h = 0; h < 2; h++)
#pragma unroll
                    for (int hf = 0; hf < 2; hf++) {
                        int nf = h * 2 + hf;
                        float g = acc[mf][nf][rr * 2 + 0];
                        float u = acc[mf][nf][rr * 2 + 1];
                        float hv = g / (1.f + __expf(-g)) * u * gsc;
                        __half hh = __float2half_rn(hv);
                        __half hl = __float2half_rn(hv - __half2float(hh));
                        int f = f0 + warpN * 16 + h * 8 + hf * 4 + (lane & 3);
                        g_Hh[hrow + f] = hh;
                        g_Hl[hrow + f] = hl;
                    }
            }
        }
    }
}

// ---------------- GEMM 2: H @ Wd^T -> atomicAdd out ----------------
__global__ __launch_bounds__(256, 1) void down_mma(float* __restrict__ out, int T)
{
    __shared__ int tok_s[TM];
    extern __shared__ __align__(16) char dynraw[];

    int z  = blockIdx.z;
    int m0 = blockIdx.x * TM;
    int d0 = blockIdx.y * 128;
    int tid = threadIdx.x, wid = tid >> 5, lane = tid & 31;
    int warpM = wid >> 2, warpN = wid & 3;

    int cnt, hbase;
    const __half* W;
    if (z < N_EXP) {
        int c = g_cnt[z];
        if (m0 >= c) return;
        cnt   = min(TM, c - m0);
        W     = g_ednw + (size_t)z * D_MODEL * D_FF;
        hbase = MAX_T + g_off[z] + m0;
        if (tid < TM) tok_s[tid] = (tid < cnt) ? g_list[z * MAX_T + m0 + tid] : 0;
    } else {
        if (m0 >= T) return;
        cnt   = min(TM, T - m0);
        W     = g_sdnw;
        hbase = m0;
        if (tid < TM) tok_s[tid] = m0 + tid;
    }
    __syncthreads();

    char*    dynp = (char*)(((uintptr_t)dynraw + 1023) & ~(uintptr_t)1023);
    uint32_t sb   = smem_u32(dynp);

    auto load_stage = [&](int s) {
        int kk = s * KC;
        uint32_t base = sb + (s & 1) * STAGE_B;
#pragma unroll
        for (int j = 0; j < 4; j++) {
            int within = tid + j * 256;
            int row = within >> 3, col = within & 7;
            uint32_t so = SWZ(row * 128 + col * 16);
            size_t ho = (size_t)(hbase + row) * D_FF + kk + col * 8;
            cp16(base + so,          g_Hh + ho);
            cp16(base + TILE_B + so, g_Hl + ho);
            size_t wo = (size_t)(d0 + row) * D_FF + kk + col * 8;
            cp16(base + 2 * TILE_B + so, W + wo);
        }
        CP_COMMIT();
    };

    float acc[4][4][4] = {};

    load_stage(0);
    for (int s = 0; s < NCH; s++) {
        if (s + 1 < NCH) { load_stage(s + 1); CP_WAIT(1); }
        else             { CP_WAIT(0); }
        __syncthreads();
        uint32_t base = sb + (s & 1) * STAGE_B;
#pragma unroll
        for (int ks = 0; ks < 4; ks++) {
            int kb = ks * 32 + (lane >> 4) * 16;
            uint32_t aH[4][4], aL[4][4], br[2][4];
            int arow = warpM * 64 + (lane & 15);
#pragma unroll
            for (int mf = 0; mf < 4; mf++) {
                uint32_t off = SWZ((arow + mf * 16) * 128 + kb);
                ldm4(aH[mf], base + off);
                ldm4(aL[mf], base + TILE_B + off);
            }
            int brow = warpN * 32 + (lane & 15);
#pragma unroll
            for (int h = 0; h < 2; h++) {
                uint32_t off = SWZ((brow + h * 16) * 128 + kb);
                ldm4(br[h], base + 2 * TILE_B + off);
            }
#pragma unroll
            for (int mf = 0; mf < 4; mf++)
#pragma unroll
                for (int h = 0; h < 2; h++)
#pragma unroll
                    for (int hf = 0; hf < 2; hf++) {
                        int nf = h * 2 + hf;
                        mma16816(acc[mf][nf], aH[mf], br[h][hf], br[h][hf + 2]);
                        mma16816(acc[mf][nf], aL[mf], br[h][hf], br[h][hf + 2]);
                    }
        }
        __syncthreads();
    }

#pragma unroll
    for (int mf = 0; mf < 4; mf++) {
        int rbase = warpM * 64 + mf * 16 + (lane >> 2);
#pragma unroll
        for (int rr = 0; rr < 2; rr++) {
            int r = rbase + rr * 8;
            if (r < cnt) {
                float* orow = out + (size_t)tok_s[r] * D_MODEL;
#pragma unroll
                for (int h = 0; h < 2; h++)
#pragma unroll
                    for (int hf = 0; hf < 2; hf++) {
                        int nf = h * 2 + hf;
                        int c  = d0 + warpN * 32 + h * 16 + hf * 8 + (lane & 3) * 2;
                        atomicAdd(orow + c,     acc[mf][nf][rr * 2 + 0]);
                        atomicAdd(orow + c + 1, acc[mf][nf][rr * 2 + 1]);
                    }
            }
        }
    }
}

// ---------------- launch ----------------
extern "C" void kernel_launch(void* const* d_in, const int* in_sizes, int n_in,
                              void* d_out, int out_size)
{
    const float* x    = (const float*)d_in[0];
    const float* gw   = (const float*)d_in[1];
    const float* bias = (const float*)d_in[2];
    const float* sgu  = (const float*)d_in[3];
    const float* sdn  = (const float*)d_in[4];
    const float* egu  = (const float*)d_in[5];
    const float* edn  = (const float*)d_in[6];
    float* out = (float*)d_out;
    int T = in_sizes[0] / D_MODEL;

    cudaFuncSetAttribute(gu_mma,   cudaFuncAttributeMaxDynamicSharedMemorySize, DYN_B);
    cudaFuncSetAttribute(down_mma, cudaFuncAttributeMaxDynamicSharedMemorySize, DYN_B);

    void *xh, *xl, *sguw, *sdnw, *eguw, *ednw;
    cudaGetSymbolAddress(&xh,   g_xh);   cudaGetSymbolAddress(&xl,   g_xl);
    cudaGetSymbolAddress(&sguw, g_sguw); cudaGetSymbolAddress(&sdnw, g_sdnw);
    cudaGetSymbolAddress(&eguw, g_eguw); cudaGetSymbolAddress(&ednw, g_ednw);

    reset_kernel<<<1, 32>>>();
    router_kernel<<<(T + 7) / 8, 256>>>(x, gw, bias, T);
    scan_kernel<<<1, 1>>>();

    int nx = T * D_MODEL;
    split8_kernel<<<(nx / 8 + 255) / 256, 256>>>(x, (__half*)xh, (__half*)xl, nx);

    int ngu  = 2 * D_FF * D_MODEL;
    int ndn  = D_MODEL * D_FF;
    int negu = N_EXP * 2 * D_FF * D_MODEL;
    int nedn = N_EXP * D_MODEL * D_FF;
    conv16_kernel<<<(ngu  / 16 + 255) / 256, 256>>>(sgu, (__half*)sguw, ngu);
    conv16_kernel<<<(negu / 16 + 255) / 256, 256>>>(egu, (__half*)eguw, negu);
    conv16_kernel<<<(ndn  / 16 + 255) / 256, 256>>>(sdn, (__half*)sdnw, ndn);
    conv16_kernel<<<(nedn / 16 + 255) / 256, 256>>>(edn, (__half*)ednw, nedn);

    cudaMemsetAsync(out, 0, (size_t)out_size * sizeof(float), 0);

    gu_mma<<<dim3(MAX_T / TM, D_FF / 64, N_EXP + 1), 256, DYN_B>>>(T);
    down_mma<<<dim3(MAX_T / TM, D_MODEL / 128, N_EXP + 1), 256, DYN_B>>>(out, T);
}

// round 6
// speedup vs baseline: 3.0158x; 1.1228x over previous
#include <cuda_runtime.h>
#include <cuda_fp16.h>
#include <math.h>
#include <stdint.h>

#define D_MODEL 512
#define D_FF    512
#define N_EXP   16
#define TOPK    3
#define MAX_T   2048
#define HROWS   (MAX_T + MAX_T * TOPK + 128)

#define TM   128
#define KC   64                 // fp16 elements per K chunk (128 bytes/row)
#define NCH  8                  // 512 / 64
#define TILE_A  (TM * 128)      // 16 KB (one A tile: 128 rows x 128B)
#define OFF_AL  TILE_A
#define OFF_B   (2 * TILE_A)    // B tile: 256 rows x 128B = 32 KB
#define STAGE_B (4 * TILE_A)    // 64 KB per stage
#define DYN_B   (2 * STAGE_B + 1024)

#define SWZ(o) ((o) ^ (((o) >> 3) & 0x70))

// ---------------- static scratch ----------------
__device__ int   g_cnt[N_EXP];
__device__ int   g_off[N_EXP + 1];
__device__ int   g_list[N_EXP * MAX_T];
__device__ float g_gate[N_EXP * MAX_T];

__device__ __align__(256) __half g_xh[MAX_T * D_MODEL];
__device__ __align__(256) __half g_xl[MAX_T * D_MODEL];
__device__ __align__(256) __half g_sguw[2 * D_FF * D_MODEL];
__device__ __align__(256) __half g_sdnw[D_MODEL * D_FF];
__device__ __align__(256) __half g_eguw[N_EXP * 2 * D_FF * D_MODEL];
__device__ __align__(256) __half g_ednw[N_EXP * D_MODEL * D_FF];
__device__ __align__(256) __half g_Hh[(size_t)HROWS * D_FF];
__device__ __align__(256) __half g_Hl[(size_t)HROWS * D_FF];

// ---------------- PTX helpers ----------------
__device__ __forceinline__ uint32_t smem_u32(const void* p) {
    uint32_t a;
    asm("{ .reg .u64 t; cvta.to.shared.u64 t, %1; cvt.u32.u64 %0, t; }" : "=r"(a) : "l"(p));
    return a;
}
__device__ __forceinline__ void cp16(uint32_t s, const void* g) {
    asm volatile("cp.async.cg.shared.global [%0], [%1], 16;" :: "r"(s), "l"(g));
}
#define CP_COMMIT() asm volatile("cp.async.commit_group;")
#define CP_WAIT(n)  asm volatile("cp.async.wait_group %0;" :: "n"(n))

__device__ __forceinline__ void ldm4(uint32_t* r, uint32_t a) {
    asm volatile("ldmatrix.sync.aligned.m8n8.x4.shared.b16 {%0,%1,%2,%3}, [%4];"
                 : "=r"(r[0]), "=r"(r[1]), "=r"(r[2]), "=r"(r[3]) : "r"(a));
}
__device__ __forceinline__ void mma16816(float* c, const uint32_t* a, uint32_t b0, uint32_t b1) {
    asm volatile("mma.sync.aligned.m16n8k16.row.col.f32.f16.f16.f32 "
                 "{%0,%1,%2,%3}, {%4,%5,%6,%7}, {%8,%9}, {%0,%1,%2,%3};"
                 : "+f"(c[0]), "+f"(c[1]), "+f"(c[2]), "+f"(c[3])
                 : "r"(a[0]), "r"(a[1]), "r"(a[2]), "r"(a[3]), "r"(b0), "r"(b1));
}

// ---------------- small kernels ----------------
__global__ void reset_kernel() {
    if (threadIdx.x < N_EXP) g_cnt[threadIdx.x] = 0;
}

// all weight tensors fp32 -> fp16 in one segmented launch (16 elts/thread)
__global__ __launch_bounds__(256) void conv_all_kernel(
    const float* __restrict__ s0, __half* __restrict__ d0, int n0,
    const float* __restrict__ s1, __half* __restrict__ d1, int n1,
    const float* __restrict__ s2, __half* __restrict__ d2, int n2,
    const float* __restrict__ s3, __half* __restrict__ d3, int n3)
{
    int total  = n0 + n1 + n2 + n3;
    int stride = gridDim.x * 256 * 16;
    for (int i0 = (blockIdx.x * 256 + threadIdx.x) * 16; i0 < total; i0 += stride) {
        const float* src;
        __half* dst;
        int off = i0;
        if (off < n0)                 { src = s0; dst = d0; }
        else if ((off -= n0) < n1)    { src = s1; dst = d1; }
        else if ((off -= n1) < n2)    { src = s2; dst = d2; }
        else { off -= n2;               src = s3; dst = d3; }
        float4 v[4];
#pragma unroll
        for (int q = 0; q < 4; q++) v[q] = *(const float4*)(src + off + q * 4);
        uint2 o[4];
#pragma unroll
        for (int q = 0; q < 4; q++) {
            __half2 p0 = __floats2half2_rn(v[q].x, v[q].y);
            __half2 p1 = __floats2half2_rn(v[q].z, v[q].w);
            o[q].x = *(uint32_t*)&p0;
            o[q].y = *(uint32_t*)&p1;
        }
        *(uint4*)(dst + off)     = make_uint4(o[0].x, o[0].y, o[1].x, o[1].y);
        *(uint4*)(dst + off + 8) = make_uint4(o[2].x, o[2].y, o[3].x, o[3].y);
    }
}

// fp32 -> fp16 hi/lo split (x), 8 elts/thread
__global__ __launch_bounds__(256) void split8_kernel(
    const float* __restrict__ src, __half* __restrict__ h,
    __half* __restrict__ l, int n)
{
    int stride = gridDim.x * 256 * 8;
    for (int i0 = (blockIdx.x * 256 + threadIdx.x) * 8; i0 < n; i0 += stride) {
        float4 a = *(const float4*)(src + i0);
        float4 b = *(const float4*)(src + i0 + 4);
        float vv[8] = {a.x, a.y, a.z, a.w, b.x, b.y, b.z, b.w};
        __half hh[8], hl[8];
#pragma unroll
        for (int q = 0; q < 8; q++) {
            hh[q] = __float2half_rn(vv[q]);
            hl[q] = __float2half_rn(vv[q] - __half2float(hh[q]));
        }
        *(uint4*)(h + i0) = *(uint4*)hh;
        *(uint4*)(l + i0) = *(uint4*)hl;
    }
}

__global__ __launch_bounds__(256) void router_kernel(
    const float* __restrict__ x, const float* __restrict__ gw,
    const float* __restrict__ bias, int T)
{
    int w    = threadIdx.x >> 5;
    int lane = threadIdx.x & 31;
    int t    = blockIdx.x * 8 + w;
    if (t >= T) return;

    const float* xr = x + (size_t)t * D_MODEL;
    float xv[16];
#pragma unroll
    for (int i = 0; i < 16; i++) xv[i] = xr[lane + 32 * i];

    __shared__ float aff_s[8][N_EXP];
    for (int e = 0; e < N_EXP; e++) {
        const float* wr = gw + (size_t)e * D_MODEL;
        float p = 0.f;
#pragma unroll
        for (int i = 0; i < 16; i++) p += xv[i] * wr[lane + 32 * i];
#pragma unroll
        for (int o = 16; o; o >>= 1) p += __shfl_xor_sync(0xffffffffu, p, o);
        if (lane == 0) aff_s[w][e] = 1.f / (1.f + expf(-p));
    }
    __syncwarp();

    if (lane == 0) {
        float aff[N_EXP], sc[N_EXP];
        bool used[N_EXP];
#pragma unroll
        for (int e = 0; e < N_EXP; e++) {
            aff[e] = aff_s[w][e];
            sc[e]  = aff[e] + bias[e];
            used[e] = false;
        }
        int   sel[TOPK];
        float sa[TOPK];
        float ssum = 0.f;
        for (int k = 0; k < TOPK; k++) {
            int best = -1; float bv = -1e30f;
            for (int e = 0; e < N_EXP; e++)
                if (!used[e] && sc[e] > bv) { bv = sc[e]; best = e; }
            used[best] = true;
            sel[k] = best; sa[k] = aff[best]; ssum += aff[best];
        }
        float inv = 1.f / (ssum + 1e-9f);
        for (int k = 0; k < TOPK; k++) {
            int e   = sel[k];
            int pos = atomicAdd(&g_cnt[e], 1);
            g_list[e * MAX_T + pos] = t;
            g_gate[e * MAX_T + pos] = sa[k] * inv;
        }
    }
}

__global__ void scan_kernel() {
    int s = 0;
    for (int e = 0; e < N_EXP; e++) { g_off[e] = s; s += g_cnt[e]; }
    g_off[N_EXP] = s;
}

// ---------------- GEMM 1: x @ Wgu^T -> SwiGLU -> H (fp16 hi/lo) ----------------
// Block: 128 rows x 128 features. B tile = 256 interleaved rows (2j=gate f0+j, 2j+1=up f0+j).
// 8 warps as 2(M) x 4(N): warp tile 64 rows x 32 features (64 B rows).
__global__ __launch_bounds__(256, 1) void gu_mma(int T)
{
    __shared__ int   tok_s[TM];
    __shared__ float gsc_s[TM];
    extern __shared__ __align__(16) char dynraw[];

    int z  = blockIdx.z;
    int m0 = blockIdx.x * TM;
    int f0 = blockIdx.y * 128;
    int tid = threadIdx.x, wid = tid >> 5, lane = tid & 31;
    int warpM = wid >> 2, warpN = wid & 3;

    int cnt, hbase;
    const __half* W;
    if (z < N_EXP) {
        int c = g_cnt[z];
        if (m0 >= c) return;
        cnt   = min(TM, c - m0);
        W     = g_eguw + (size_t)z * 2 * D_FF * D_MODEL;
        hbase = MAX_T + g_off[z] + m0;
        if (tid < TM) {
            if (tid < cnt) {
                tok_s[tid] = g_list[z * MAX_T + m0 + tid];
                gsc_s[tid] = g_gate[z * MAX_T + m0 + tid];
            } else { tok_s[tid] = 0; gsc_s[tid] = 0.f; }
        }
    } else {
        if (m0 >= T) return;
        cnt   = min(TM, T - m0);
        W     = g_sguw;
        hbase = m0;
        if (tid < TM) { tok_s[tid] = m0 + tid; gsc_s[tid] = 1.f; }
    }
    __syncthreads();

    char*    dynp = (char*)(((uintptr_t)dynraw + 1023) & ~(uintptr_t)1023);
    uint32_t sb   = smem_u32(dynp);

    auto load_stage = [&](int s) {
        int kk = s * KC;
        uint32_t base = sb + (s & 1) * STAGE_B;
#pragma unroll
        for (int j = 0; j < 4; j++) {
            int w_ = tid + j * 256;
            int row = w_ >> 3, col = w_ & 7;
            uint32_t so = SWZ(row * 128 + col * 16);
            size_t xo = (size_t)tok_s[row] * D_MODEL + kk + col * 8;
            cp16(base + so,          g_xh + xo);
            cp16(base + OFF_AL + so, g_xl + xo);
        }
#pragma unroll
        for (int j = 0; j < 8; j++) {
            int w_ = tid + j * 256;
            int row = w_ >> 3, col = w_ & 7;           // row 0..255
            uint32_t so = SWZ(row * 128 + col * 16);
            int wr = (row & 1) ? (D_FF + f0 + (row >> 1)) : (f0 + (row >> 1));
            cp16(base + OFF_B + so, W + (size_t)wr * D_MODEL + kk + col * 8);
        }
        CP_COMMIT();
    };

    float acc[4][8][4] = {};

    load_stage(0);
    for (int s = 0; s < NCH; s++) {
        if (s + 1 < NCH) { load_stage(s + 1); CP_WAIT(1); }
        else             { CP_WAIT(0); }
        __syncthreads();
        uint32_t base = sb + (s & 1) * STAGE_B;
#pragma unroll
        for (int ks = 0; ks < 4; ks++) {
            int kb = ks * 32 + (lane >> 4) * 16;
            uint32_t a[4][4], br[4][4];
            int arow = warpM * 64 + (lane & 15);
            int brow = warpN * 64 + (lane & 15);
#pragma unroll
            for (int h = 0; h < 4; h++)
                ldm4(br[h], base + OFF_B + SWZ((brow + h * 16) * 128 + kb));
#pragma unroll
            for (int mf = 0; mf < 4; mf++)
                ldm4(a[mf], base + SWZ((arow + mf * 16) * 128 + kb));
#pragma unroll
            for (int mf = 0; mf < 4; mf++)
#pragma unroll
                for (int h = 0; h < 4; h++)
#pragma unroll
                    for (int hf = 0; hf < 2; hf++)
                        mma16816(acc[mf][h * 2 + hf], a[mf], br[h][hf], br[h][hf + 2]);
#pragma unroll
            for (int mf = 0; mf < 4; mf++)
                ldm4(a[mf], base + OFF_AL + SWZ((arow + mf * 16) * 128 + kb));
#pragma unroll
            for (int mf = 0; mf < 4; mf++)
#pragma unroll
                for (int h = 0; h < 4; h++)
#pragma unroll
                    for (int hf = 0; hf < 2; hf++)
                        mma16816(acc[mf][h * 2 + hf], a[mf], br[h][hf], br[h][hf + 2]);
        }
        __syncthreads();
    }

    // epilogue: (c even, c odd) = (gate, up) of one feature
#pragma unroll
    for (int mf = 0; mf < 4; mf++) {
        int rbase = warpM * 64 + mf * 16 + (lane >> 2);
#pragma unroll
        for (int rr = 0; rr < 2; rr++) {
            int r = rbase + rr * 8;
            if (r < cnt) {
                float gsc = gsc_s[r];
                size_t hrow = (size_t)(hbase + r) * D_FF;
#pragma unroll
                for (int h = 0; h < 4; h++)
#pragma unroll
                    for (int hf = 0; hf < 2; hf++) {
                        int nf = h * 2 + hf;
                        float g = acc[mf][nf][rr * 2 + 0];
                        float u = acc[mf][nf][rr * 2 + 1];
                        float hv = g / (1.f + __expf(-g)) * u * gsc;
                        __half hh = __float2half_rn(hv);
                        __half hl = __float2half_rn(hv - __half2float(hh));
                        int f = f0 + warpN * 32 + h * 8 + hf * 4 + (lane & 3);
                        g_Hh[hrow + f] = hh;
                        g_Hl[hrow + f] = hl;
                    }
            }
        }
    }
}

// ---------------- GEMM 2: H @ Wd^T -> atomicAdd out ----------------
// Block: 128 rows x 256 output cols (256 B rows). Warp tile 64 x 64.
__global__ __launch_bounds__(256, 1) void down_mma(float* __restrict__ out, int T)
{
    __shared__ int tok_s[TM];
    extern __shared__ __align__(16) char dynraw[];

    int z  = blockIdx.z;
    int m0 = blockIdx.x * TM;
    int d0 = blockIdx.y * 256;
    int tid = threadIdx.x, wid = tid >> 5, lane = tid & 31;
    int warpM = wid >> 2, warpN = wid & 3;

    int cnt, hbase;
    const __half* W;
    if (z < N_EXP) {
        int c = g_cnt[z];
        if (m0 >= c) return;
        cnt   = min(TM, c - m0);
        W     = g_ednw + (size_t)z * D_MODEL * D_FF;
        hbase = MAX_T + g_off[z] + m0;
        if (tid < TM) tok_s[tid] = (tid < cnt) ? g_list[z * MAX_T + m0 + tid] : 0;
    } else {
        if (m0 >= T) return;
        cnt   = min(TM, T - m0);
        W     = g_sdnw;
        hbase = m0;
        if (tid < TM) tok_s[tid] = m0 + tid;
    }
    __syncthreads();

    char*    dynp = (char*)(((uintptr_t)dynraw + 1023) & ~(uintptr_t)1023);
    uint32_t sb   = smem_u32(dynp);

    auto load_stage = [&](int s) {
        int kk = s * KC;
        uint32_t base = sb + (s & 1) * STAGE_B;
#pragma unroll
        for (int j = 0; j < 4; j++) {
            int w_ = tid + j * 256;
            int row = w_ >> 3, col = w_ & 7;
            uint32_t so = SWZ(row * 128 + col * 16);
            size_t ho = (size_t)(hbase + row) * D_FF + kk + col * 8;
            cp16(base + so,          g_Hh + ho);
            cp16(base + OFF_AL + so, g_Hl + ho);
        }
#pragma unroll
        for (int j = 0; j < 8; j++) {
            int w_ = tid + j * 256;
            int row = w_ >> 3, col = w_ & 7;           // row 0..255
            uint32_t so = SWZ(row * 128 + col * 16);
            cp16(base + OFF_B + so, W + (size_t)(d0 + row) * D_FF + kk + col * 8);
        }
        CP_COMMIT();
    };

    float acc[4][8][4] = {};

    load_stage(0);
    for (int s = 0; s < NCH; s++) {
        if (s + 1 < NCH) { load_stage(s + 1); CP_WAIT(1); }
        else             { CP_WAIT(0); }
        __syncthreads();
        uint32_t base = sb + (s & 1) * STAGE_B;
#pragma unroll
        for (int ks = 0; ks < 4; ks++) {
            int kb = ks * 32 + (lane >> 4) * 16;
            uint32_t a[4][4], br[4][4];
            int arow = warpM * 64 + (lane & 15);
            int brow = warpN * 64 + (lane & 15);
#pragma unroll
            for (int h = 0; h < 4; h++)
                ldm4(br[h], base + OFF_B + SWZ((brow + h * 16) * 128 + kb));
#pragma unroll
            for (int mf = 0; mf < 4; mf++)
                ldm4(a[mf], base + SWZ((arow + mf * 16) * 128 + kb));
#pragma unroll
            for (int mf = 0; mf < 4; mf++)
#pragma unroll
                for (int h = 0; h < 4; h++)
#pragma unroll
                    for (int hf = 0; hf < 2; hf++)
                        mma16816(acc[mf][h * 2 + hf], a[mf], br[h][hf], br[h][hf + 2]);
#pragma unroll
            for (int mf = 0; mf < 4; mf++)
                ldm4(a[mf], base + OFF_AL + SWZ((arow + mf * 16) * 128 + kb));
#pragma unroll
            for (int mf = 0; mf < 4; mf++)
#pragma unroll
                for (int h = 0; h < 4; h++)
#pragma unroll
                    for (int hf = 0; hf < 2; hf++)
                        mma16816(acc[mf][h * 2 + hf], a[mf], br[h][hf], br[h][hf + 2]);
        }
        __syncthreads();
    }

#pragma unroll
    for (int mf = 0; mf < 4; mf++) {
        int rbase = warpM * 64 + mf * 16 + (lane >> 2);
#pragma unroll
        for (int rr = 0; rr < 2; rr++) {
            int r = rbase + rr * 8;
            if (r < cnt) {
                float* orow = out + (size_t)tok_s[r] * D_MODEL;
#pragma unroll
                for (int h = 0; h < 4; h++)
#pragma unroll
                    for (int hf = 0; hf < 2; hf++) {
                        int nf = h * 2 + hf;
                        int c  = d0 + warpN * 64 + h * 16 + hf * 8 + (lane & 3) * 2;
                        atomicAdd(orow + c,     acc[mf][nf][rr * 2 + 0]);
                        atomicAdd(orow + c + 1, acc[mf][nf][rr * 2 + 1]);
                    }
            }
        }
    }
}

// ---------------- launch ----------------
extern "C" void kernel_launch(void* const* d_in, const int* in_sizes, int n_in,
                              void* d_out, int out_size)
{
    const float* x    = (const float*)d_in[0];
    const float* gw   = (const float*)d_in[1];
    const float* bias = (const float*)d_in[2];
    const float* sgu  = (const float*)d_in[3];
    const float* sdn  = (const float*)d_in[4];
    const float* egu  = (const float*)d_in[5];
    const float* edn  = (const float*)d_in[6];
    float* out = (float*)d_out;
    int T = in_sizes[0] / D_MODEL;

    cudaFuncSetAttribute(gu_mma,   cudaFuncAttributeMaxDynamicSharedMemorySize, DYN_B);
    cudaFuncSetAttribute(down_mma, cudaFuncAttributeMaxDynamicSharedMemorySize, DYN_B);

    void *xh, *xl, *sguw, *sdnw, *eguw, *ednw;
    cudaGetSymbolAddress(&xh,   g_xh);   cudaGetSymbolAddress(&xl,   g_xl);
    cudaGetSymbolAddress(&sguw, g_sguw); cudaGetSymbolAddress(&sdnw, g_sdnw);
    cudaGetSymbolAddress(&eguw, g_eguw); cudaGetSymbolAddress(&ednw, g_ednw);

    reset_kernel<<<1, 32>>>();
    router_kernel<<<(T + 7) / 8, 256>>>(x, gw, bias, T);
    scan_kernel<<<1, 1>>>();

    int nx = T * D_MODEL;
    split8_kernel<<<(nx / 8 + 255) / 256, 256>>>(x, (__half*)xh, (__half*)xl, nx);

    int ngu  = 2 * D_FF * D_MODEL;
    int ndn  = D_MODEL * D_FF;
    int negu = N_EXP * 2 * D_FF * D_MODEL;
    int nedn = N_EXP * D_MODEL * D_FF;
    int ntot = ngu + ndn + negu + nedn;
    conv_all_kernel<<<(ntot / 16 + 255) / 256, 256>>>(
        sgu, (__half*)sguw, ngu,
        egu, (__half*)eguw, negu,
        sdn, (__half*)sdnw, ndn,
        edn, (__half*)ednw, nedn);

    cudaMemsetAsync(out, 0, (size_t)out_size * sizeof(float), 0);

    gu_mma<<<dim3(MAX_T / TM, D_FF / 128, N_EXP + 1), 256, DYN_B>>>(T);
    down_mma<<<dim3(MAX_T / TM, D_MODEL / 256, N_EXP + 1), 256, DYN_B>>>(out, T);
}

// round 7
// speedup vs baseline: 4.2503x; 1.4093x over previous
#include <cuda_runtime.h>
#include <cuda_fp16.h>
#include <math.h>
#include <stdint.h>

#define D_MODEL 512
#define D_FF    512
#define N_EXP   16
#define TOPK    3
#define MAX_T   2048
#define HROWS   (MAX_T + MAX_T * TOPK + 128)

#define TM   128
#define KC   64                 // fp16 elements per K chunk (128 bytes/row)
#define NCH  8                  // 512 / 64
#define TILE_A  (TM * 128)      // 16 KB (A tile: 128 rows x 128B)
#define OFF_B   TILE_A          // B tile: 256 rows x 128B = 32 KB
#define STAGE_B (3 * TILE_A)    // 48 KB per stage
#define NSTG 3
#define DYN_B   (NSTG * STAGE_B + 1024)

#define SWZ(o) ((o) ^ (((o) >> 3) & 0x70))

// ---------------- static scratch ----------------
__device__ int   g_cnt[N_EXP];
__device__ int   g_off[N_EXP + 1];
__device__ int   g_list[N_EXP * MAX_T];
__device__ float g_gate[N_EXP * MAX_T];

__device__ __align__(256) __half g_xw[MAX_T * D_MODEL];
__device__ __align__(256) __half g_sguw[2 * D_FF * D_MODEL];
__device__ __align__(256) __half g_sdnw[D_MODEL * D_FF];
__device__ __align__(256) __half g_eguw[N_EXP * 2 * D_FF * D_MODEL];
__device__ __align__(256) __half g_ednw[N_EXP * D_MODEL * D_FF];
__device__ __align__(256) __half g_H[(size_t)HROWS * D_FF];

// ---------------- PTX helpers ----------------
__device__ __forceinline__ uint32_t smem_u32(const void* p) {
    uint32_t a;
    asm("{ .reg .u64 t; cvta.to.shared.u64 t, %1; cvt.u32.u64 %0, t; }" : "=r"(a) : "l"(p));
    return a;
}
__device__ __forceinline__ void cp16(uint32_t s, const void* g) {
    asm volatile("cp.async.cg.shared.global [%0], [%1], 16;" :: "r"(s), "l"(g));
}
#define CP_COMMIT() asm volatile("cp.async.commit_group;")
#define CP_WAIT(n)  asm volatile("cp.async.wait_group %0;" :: "n"(n))

__device__ __forceinline__ void ldm4(uint32_t* r, uint32_t a) {
    asm volatile("ldmatrix.sync.aligned.m8n8.x4.shared.b16 {%0,%1,%2,%3}, [%4];"
                 : "=r"(r[0]), "=r"(r[1]), "=r"(r[2]), "=r"(r[3]) : "r"(a));
}
__device__ __forceinline__ void mma16816(float* c, const uint32_t* a, uint32_t b0, uint32_t b1) {
    asm volatile("mma.sync.aligned.m16n8k16.row.col.f32.f16.f16.f32 "
                 "{%0,%1,%2,%3}, {%4,%5,%6,%7}, {%8,%9}, {%0,%1,%2,%3};"
                 : "+f"(c[0]), "+f"(c[1]), "+f"(c[2]), "+f"(c[3])
                 : "r"(a[0]), "r"(a[1]), "r"(a[2]), "r"(a[3]), "r"(b0), "r"(b1));
}

// ---------------- small kernels ----------------
__global__ void reset_kernel() {
    if (threadIdx.x < N_EXP) g_cnt[threadIdx.x] = 0;
}

// all fp32 -> fp16 conversions in one segmented launch (16 elts/thread)
__global__ __launch_bounds__(256) void conv_all_kernel(
    const float* __restrict__ s0, __half* __restrict__ d0, int n0,
    const float* __restrict__ s1, __half* __restrict__ d1, int n1,
    const float* __restrict__ s2, __half* __restrict__ d2, int n2,
    const float* __restrict__ s3, __half* __restrict__ d3, int n3,
    const float* __restrict__ s4, __half* __restrict__ d4, int n4)
{
    int total  = n0 + n1 + n2 + n3 + n4;
    int stride = gridDim.x * 256 * 16;
    for (int i0 = (blockIdx.x * 256 + threadIdx.x) * 16; i0 < total; i0 += stride) {
        const float* src;
        __half* dst;
        int off = i0;
        if (off < n0)                 { src = s0; dst = d0; }
        else if ((off -= n0) < n1)    { src = s1; dst = d1; }
        else if ((off -= n1) < n2)    { src = s2; dst = d2; }
        else if ((off -= n2) < n3)    { src = s3; dst = d3; }
        else { off -= n3;               src = s4; dst = d4; }
        float4 v[4];
#pragma unroll
        for (int q = 0; q < 4; q++) v[q] = *(const float4*)(src + off + q * 4);
        uint2 o[4];
#pragma unroll
        for (int q = 0; q < 4; q++) {
            __half2 p0 = __floats2half2_rn(v[q].x, v[q].y);
            __half2 p1 = __floats2half2_rn(v[q].z, v[q].w);
            o[q].x = *(uint32_t*)&p0;
            o[q].y = *(uint32_t*)&p1;
        }
        *(uint4*)(dst + off)     = make_uint4(o[0].x, o[0].y, o[1].x, o[1].y);
        *(uint4*)(dst + off + 8) = make_uint4(o[2].x, o[2].y, o[3].x, o[3].y);
    }
}

__global__ __launch_bounds__(256) void router_kernel(
    const float* __restrict__ x, const float* __restrict__ gw,
    const float* __restrict__ bias, int T)
{
    int w    = threadIdx.x >> 5;
    int lane = threadIdx.x & 31;
    int t    = blockIdx.x * 8 + w;
    if (t >= T) return;

    const float* xr = x + (size_t)t * D_MODEL;
    float xv[16];
#pragma unroll
    for (int i = 0; i < 16; i++) xv[i] = xr[lane + 32 * i];

    __shared__ float aff_s[8][N_EXP];
    for (int e = 0; e < N_EXP; e++) {
        const float* wr = gw + (size_t)e * D_MODEL;
        float p = 0.f;
#pragma unroll
        for (int i = 0; i < 16; i++) p += xv[i] * wr[lane + 32 * i];
#pragma unroll
        for (int o = 16; o; o >>= 1) p += __shfl_xor_sync(0xffffffffu, p, o);
        if (lane == 0) aff_s[w][e] = 1.f / (1.f + expf(-p));
    }
    __syncwarp();

    if (lane == 0) {
        float aff[N_EXP], sc[N_EXP];
        bool used[N_EXP];
#pragma unroll
        for (int e = 0; e < N_EXP; e++) {
            aff[e] = aff_s[w][e];
            sc[e]  = aff[e] + bias[e];
            used[e] = false;
        }
        int   sel[TOPK];
        float sa[TOPK];
        float ssum = 0.f;
        for (int k = 0; k < TOPK; k++) {
            int best = -1; float bv = -1e30f;
            for (int e = 0; e < N_EXP; e++)
                if (!used[e] && sc[e] > bv) { bv = sc[e]; best = e; }
            used[best] = true;
            sel[k] = best; sa[k] = aff[best]; ssum += aff[best];
        }
        float inv = 1.f / (ssum + 1e-9f);
        for (int k = 0; k < TOPK; k++) {
            int e   = sel[k];
            int pos = atomicAdd(&g_cnt[e], 1);
            g_list[e * MAX_T + pos] = t;
            g_gate[e * MAX_T + pos] = sa[k] * inv;
        }
    }
}

__global__ void scan_kernel() {
    int s = 0;
    for (int e = 0; e < N_EXP; e++) { g_off[e] = s; s += g_cnt[e]; }
    g_off[N_EXP] = s;
}

// ---------------- GEMM 1: x @ Wgu^T -> SwiGLU -> H (fp16) ----------------
// Block: 128 rows x 128 features. B tile = 256 interleaved rows (2j=gate f0+j, 2j+1=up f0+j).
// 8 warps as 2(M) x 4(N): warp tile 64 rows x 32 features (64 B rows).
__global__ __launch_bounds__(256, 1) void gu_mma(int T)
{
    __shared__ int   tok_s[TM];
    __shared__ float gsc_s[TM];
    extern __shared__ __align__(16) char dynraw[];

    int z  = blockIdx.z;
    int m0 = blockIdx.x * TM;
    int f0 = blockIdx.y * 128;
    int tid = threadIdx.x, wid = tid >> 5, lane = tid & 31;
    int warpM = wid >> 2, warpN = wid & 3;

    int cnt, hbase;
    const __half* W;
    if (z < N_EXP) {
        int c = g_cnt[z];
        if (m0 >= c) return;
        cnt   = min(TM, c - m0);
        W     = g_eguw + (size_t)z * 2 * D_FF * D_MODEL;
        hbase = MAX_T + g_off[z] + m0;
        if (tid < TM) {
            if (tid < cnt) {
                tok_s[tid] = g_list[z * MAX_T + m0 + tid];
                gsc_s[tid] = g_gate[z * MAX_T + m0 + tid];
            } else { tok_s[tid] = 0; gsc_s[tid] = 0.f; }
        }
    } else {
        if (m0 >= T) return;
        cnt   = min(TM, T - m0);
        W     = g_sguw;
        hbase = m0;
        if (tid < TM) { tok_s[tid] = m0 + tid; gsc_s[tid] = 1.f; }
    }
    __syncthreads();

    char*    dynp = (char*)(((uintptr_t)dynraw + 1023) & ~(uintptr_t)1023);
    uint32_t sb   = smem_u32(dynp);

    auto load_stage = [&](int s) {
        int kk = s * KC;
        uint32_t base = sb + (s % NSTG) * STAGE_B;
#pragma unroll
        for (int j = 0; j < 4; j++) {
            int w_ = tid + j * 256;
            int row = w_ >> 3, col = w_ & 7;
            uint32_t so = SWZ(row * 128 + col * 16);
            cp16(base + so, g_xw + (size_t)tok_s[row] * D_MODEL + kk + col * 8);
        }
#pragma unroll
        for (int j = 0; j < 8; j++) {
            int w_ = tid + j * 256;
            int row = w_ >> 3, col = w_ & 7;           // row 0..255
            uint32_t so = SWZ(row * 128 + col * 16);
            int wr = (row & 1) ? (D_FF + f0 + (row >> 1)) : (f0 + (row >> 1));
            cp16(base + OFF_B + so, W + (size_t)wr * D_MODEL + kk + col * 8);
        }
        CP_COMMIT();
    };

    float acc[4][8][4] = {};

    load_stage(0);
    load_stage(1);
    for (int s = 0; s < NCH; s++) {
        if (s + 2 < NCH)      { load_stage(s + 2); CP_WAIT(2); }
        else if (s + 1 < NCH) { CP_WAIT(1); }
        else                  { CP_WAIT(0); }
        __syncthreads();
        uint32_t base = sb + (s % NSTG) * STAGE_B;
#pragma unroll
        for (int ks = 0; ks < 4; ks++) {
            int kb = ks * 32 + (lane >> 4) * 16;
            uint32_t a[4][4], br[4][4];
            int arow = warpM * 64 + (lane & 15);
            int brow = warpN * 64 + (lane & 15);
#pragma unroll
            for (int h = 0; h < 4; h++)
                ldm4(br[h], base + OFF_B + SWZ((brow + h * 16) * 128 + kb));
#pragma unroll
            for (int mf = 0; mf < 4; mf++)
                ldm4(a[mf], base + SWZ((arow + mf * 16) * 128 + kb));
#pragma unroll
            for (int mf = 0; mf < 4; mf++)
#pragma unroll
                for (int h = 0; h < 4; h++)
#pragma unroll
                    for (int hf = 0; hf < 2; hf++)
                        mma16816(acc[mf][h * 2 + hf], a[mf], br[h][hf], br[h][hf + 2]);
        }
        __syncthreads();
    }

    // epilogue: (c even, c odd) = (gate, up) of one feature
#pragma unroll
    for (int mf = 0; mf < 4; mf++) {
        int rbase = warpM * 64 + mf * 16 + (lane >> 2);
#pragma unroll
        for (int rr = 0; rr < 2; rr++) {
            int r = rbase + rr * 8;
            if (r < cnt) {
                float gsc = gsc_s[r];
                size_t hrow = (size_t)(hbase + r) * D_FF;
#pragma unroll
                for (int h = 0; h < 4; h++)
#pragma unroll
                    for (int hf = 0; hf < 2; hf++) {
                        int nf = h * 2 + hf;
                        float g = acc[mf][nf][rr * 2 + 0];
                        float u = acc[mf][nf][rr * 2 + 1];
                        float hv = g / (1.f + __expf(-g)) * u * gsc;
                        int f = f0 + warpN * 32 + h * 8 + hf * 4 + (lane & 3);
                        g_H[hrow + f] = __float2half_rn(hv);
                    }
            }
        }
    }
}

// ---------------- GEMM 2: H @ Wd^T -> atomicAdd out ----------------
// Block: 128 rows x 256 output cols (256 B rows). Warp tile 64 x 64.
__global__ __launch_bounds__(256, 1) void down_mma(float* __restrict__ out, int T)
{
    __shared__ int tok_s[TM];
    extern __shared__ __align__(16) char dynraw[];

    int z  = blockIdx.z;
    int m0 = blockIdx.x * TM;
    int d0 = blockIdx.y * 256;
    int tid = threadIdx.x, wid = tid >> 5, lane = tid & 31;
    int warpM = wid >> 2, warpN = wid & 3;

    int cnt, hbase;
    const __half* W;
    if (z < N_EXP) {
        int c = g_cnt[z];
        if (m0 >= c) return;
        cnt   = min(TM, c - m0);
        W     = g_ednw + (size_t)z * D_MODEL * D_FF;
        hbase = MAX_T + g_off[z] + m0;
        if (tid < TM) tok_s[tid] = (tid < cnt) ? g_list[z * MAX_T + m0 + tid] : 0;
    } else {
        if (m0 >= T) return;
        cnt   = min(TM, T - m0);
        W     = g_sdnw;
        hbase = m0;
        if (tid < TM) tok_s[tid] = m0 + tid;
    }
    __syncthreads();

    char*    dynp = (char*)(((uintptr_t)dynraw + 1023) & ~(uintptr_t)1023);
    uint32_t sb   = smem_u32(dynp);

    auto load_stage = [&](int s) {
        int kk = s * KC;
        uint32_t base = sb + (s % NSTG) * STAGE_B;
#pragma unroll
        for (int j = 0; j < 4; j++) {
            int w_ = tid + j * 256;
            int row = w_ >> 3, col = w_ & 7;
            uint32_t so = SWZ(row * 128 + col * 16);
            cp16(base + so, g_H + (size_t)(hbase + row) * D_FF + kk + col * 8);
        }
#pragma unroll
        for (int j = 0; j < 8; j++) {
            int w_ = tid + j * 256;
            int row = w_ >> 3, col = w_ & 7;           // row 0..255
            uint32_t so = SWZ(row * 128 + col * 16);
            cp16(base + OFF_B + so, W + (size_t)(d0 + row) * D_FF + kk + col * 8);
        }
        CP_COMMIT();
    };

    float acc[4][8][4] = {};

    load_stage(0);
    load_stage(1);
    for (int s = 0; s < NCH; s++) {
        if (s + 2 < NCH)      { load_stage(s + 2); CP_WAIT(2); }
        else if (s + 1 < NCH) { CP_WAIT(1); }
        else                  { CP_WAIT(0); }
        __syncthreads();
        uint32_t base = sb + (s % NSTG) * STAGE_B;
#pragma unroll
        for (int ks = 0; ks < 4; ks++) {
            int kb = ks * 32 + (lane >> 4) * 16;
            uint32_t a[4][4], br[4][4];
            int arow = warpM * 64 + (lane & 15);
            int brow = warpN * 64 + (lane & 15);
#pragma unroll
            for (int h = 0; h < 4; h++)
                ldm4(br[h], base + OFF_B + SWZ((brow + h * 16) * 128 + kb));
#pragma unroll
            for (int mf = 0; mf < 4; mf++)
                ldm4(a[mf], base + SWZ((arow + mf * 16) * 128 + kb));
#pragma unroll
            for (int mf = 0; mf < 4; mf++)
#pragma unroll
                for (int h = 0; h < 4; h++)
#pragma unroll
                    for (int hf = 0; hf < 2; hf++)
                        mma16816(acc[mf][h * 2 + hf], a[mf], br[h][hf], br[h][hf + 2]);
        }
        __syncthreads();
    }

#pragma unroll
    for (int mf = 0; mf < 4; mf++) {
        int rbase = warpM * 64 + mf * 16 + (lane >> 2);
#pragma unroll
        for (int rr = 0; rr < 2; rr++) {
            int r = rbase + rr * 8;
            if (r < cnt) {
                float* orow = out + (size_t)tok_s[r] * D_MODEL;
#pragma unroll
                for (int h = 0; h < 4; h++)
#pragma unroll
                    for (int hf = 0; hf < 2; hf++) {
                        int nf = h * 2 + hf;
                        int c  = d0 + warpN * 64 + h * 16 + hf * 8 + (lane & 3) * 2;
                        atomicAdd(orow + c,     acc[mf][nf][rr * 2 + 0]);
                        atomicAdd(orow + c + 1, acc[mf][nf][rr * 2 + 1]);
                    }
            }
        }
    }
}

// ---------------- launch ----------------
extern "C" void kernel_launch(void* const* d_in, const int* in_sizes, int n_in,
                              void* d_out, int out_size)
{
    const float* x    = (const float*)d_in[0];
    const float* gw   = (const float*)d_in[1];
    const float* bias = (const float*)d_in[2];
    const float* sgu  = (const float*)d_in[3];
    const float* sdn  = (const float*)d_in[4];
    const float* egu  = (const float*)d_in[5];
    const float* edn  = (const float*)d_in[6];
    float* out = (float*)d_out;
    int T = in_sizes[0] / D_MODEL;

    cudaFuncSetAttribute(gu_mma,   cudaFuncAttributeMaxDynamicSharedMemorySize, DYN_B);
    cudaFuncSetAttribute(down_mma, cudaFuncAttributeMaxDynamicSharedMemorySize, DYN_B);

    void *xw, *sguw, *sdnw, *eguw, *ednw;
    cudaGetSymbolAddress(&xw,   g_xw);
    cudaGetSymbolAddress(&sguw, g_sguw); cudaGetSymbolAddress(&sdnw, g_sdnw);
    cudaGetSymbolAddress(&eguw, g_eguw); cudaGetSymbolAddress(&ednw, g_ednw);

    reset_kernel<<<1, 32>>>();
    router_kernel<<<(T + 7) / 8, 256>>>(x, gw, bias, T);
    scan_kernel<<<1, 1>>>();

    int nx   = T * D_MODEL;
    int ngu  = 2 * D_FF * D_MODEL;
    int ndn  = D_MODEL * D_FF;
    int negu = N_EXP * 2 * D_FF * D_MODEL;
    int nedn = N_EXP * D_MODEL * D_FF;
    int ntot = nx + ngu + ndn + negu + nedn;
    conv_all_kernel<<<(ntot / 16 + 255) / 256, 256>>>(
        x,   (__half*)xw,   nx,
        sgu, (__half*)sguw, ngu,
        egu, (__half*)eguw, negu,
        sdn, (__half*)sdnw, ndn,
        edn, (__half*)ednw, nedn);

    cudaMemsetAsync(out, 0, (size_t)out_size * sizeof(float), 0);

    gu_mma<<<dim3(MAX_T / TM, D_FF / 128, N_EXP + 1), 256, DYN_B>>>(T);
    down_mma<<<dim3(MAX_T / TM, D_MODEL / 256, N_EXP + 1), 256, DYN_B>>>(out, T);
}